// round 16
// baseline (speedup 1.0000x reference)
#include <cuda_runtime.h>
#include <math.h>

#define HDIM 4096
#define IDIM 4096
#define TPB  256
#define NWARP (TPB / 32)
#define GRID 3552           // 8 full waves of 444 concurrent CTAs (148 SM x occ 3)
#define EXTRA (HDIM - GRID) // 544 leading CTAs take a second row

// fast tanh via MUFU-based __expf: rel err ~1e-6, saturates correctly at +/-1
__device__ __forceinline__ float fast_tanh(float v) {
    float e = __expf(2.0f * v);          // inf for large v -> result 1
    return 1.0f - __fdividef(2.0f, e + 1.0f);
}

// Folded multi-value warp reduction: 8 gate sums in 9 shuffles.
__device__ __forceinline__ void warp_reduce8_store(const float* acc, float* dst, int lane)
{
    const bool lo16 = (lane & 16) == 0;
    float v[4];
#pragma unroll
    for (int g = 0; g < 4; ++g) {
        float keep = lo16 ? acc[g]     : acc[g + 4];
        float send = lo16 ? acc[g + 4] : acc[g];
        v[g] = keep + __shfl_xor_sync(0xFFFFFFFFu, send, 16);
    }
    const bool lo8 = (lane & 8) == 0;
    float u[2];
#pragma unroll
    for (int g = 0; g < 2; ++g) {
        float keep = lo8 ? v[g]     : v[g + 2];
        float send = lo8 ? v[g + 2] : v[g];
        u[g] = keep + __shfl_xor_sync(0xFFFFFFFFu, send, 8);
    }
    const bool lo4 = (lane & 4) == 0;
    float keep = lo4 ? u[0] : u[1];
    float send = lo4 ? u[1] : u[0];
    float w = keep + __shfl_xor_sync(0xFFFFFFFFu, send, 4);
    w += __shfl_xor_sync(0xFFFFFFFFu, w, 2);
    w += __shfl_xor_sync(0xFFFFFFFFu, w, 1);

    const int g = ((lane >> 2) & 1) | (((lane >> 3) & 1) << 1) | (((lane >> 4) & 1) << 2);
    if ((lane & 3) == 0) dst[g] = w;
}

__global__ __launch_bounds__(TPB, 3) void slstm_row_kernel(
    const float* __restrict__ x,
    const float* __restrict__ h_prev,
    const float* __restrict__ c_prev,
    const float* __restrict__ n_prev,
    const float* __restrict__ m_prev,
    const float* __restrict__ w_i,
    const float* __restrict__ w_f,
    const float* __restrict__ w_o,
    const float* __restrict__ w_z,
    const float* __restrict__ r_i,
    const float* __restrict__ r_f,
    const float* __restrict__ r_o,
    const float* __restrict__ r_z,
    const float* __restrict__ b_i,
    const float* __restrict__ b_f,
    const float* __restrict__ b_o,
    const float* __restrict__ b_z,
    float* __restrict__ out)
{
    const int tid = threadIdx.x;
    const int lane = tid & 31;
    const int warp = tid >> 5;

    const float4* xv4 = (const float4*)x;
    const float4* hv4 = (const float4*)h_prev;

    __shared__ float red[NWARP][8];

    const int nrows = (blockIdx.x < EXTRA) ? 2 : 1;

    for (int rr = 0; rr < nrows; ++rr) {
        const int row = blockIdx.x + rr * GRID;

        // ---- prefetch gating scalars (thread 0); hides under mainloop ----
        float pb_i = 0.f, pb_f = 0.f, pb_o = 0.f, pb_z = 0.f, pmp = 0.f, pcp = 0.f, pnp = 0.f;
        if (tid == 0) {
            pb_i = __ldg(b_i + row);
            pb_f = __ldg(b_f + row);
            pb_o = __ldg(b_o + row);
            pb_z = __ldg(b_z + row);
            pmp  = __ldg(m_prev + row);
            pcp  = __ldg(c_prev + row);
            pnp  = __ldg(n_prev + row);
        }

        const size_t roff = (size_t)row * IDIM;

        const float4* W0 = (const float4*)(w_i + roff);
        const float4* W1 = (const float4*)(w_f + roff);
        const float4* W2 = (const float4*)(w_o + roff);
        const float4* W3 = (const float4*)(w_z + roff);
        const float4* R0 = (const float4*)(r_i + roff);
        const float4* R1 = (const float4*)(r_f + roff);
        const float4* R2 = (const float4*)(r_o + roff);
        const float4* R3 = (const float4*)(r_z + roff);

        float accA[8], accB[8];
#pragma unroll
        for (int g = 0; g < 8; ++g) { accA[g] = 0.0f; accB[g] = 0.0f; }

#pragma unroll
        for (int blk = 0; blk < 2; ++blk) {
            const int ka = (2 * blk + 0) * TPB + tid;
            const int kb = (2 * blk + 1) * TPB + tid;

            // ---- front-batched loads (20 x LDG.128) ----
            float4 xa = __ldg(xv4 + ka);
            float4 ha = __ldg(hv4 + ka);
            float4 xb = __ldg(xv4 + kb);
            float4 hb = __ldg(hv4 + kb);

            float4 a0 = __ldcs(W0 + ka);
            float4 a1 = __ldcs(W1 + ka);
            float4 a2 = __ldcs(W2 + ka);
            float4 a3 = __ldcs(W3 + ka);
            float4 c0 = __ldcs(R0 + ka);
            float4 c1 = __ldcs(R1 + ka);
            float4 c2 = __ldcs(R2 + ka);
            float4 c3 = __ldcs(R3 + ka);

            float4 d0 = __ldcs(W0 + kb);
            float4 d1 = __ldcs(W1 + kb);
            float4 d2 = __ldcs(W2 + kb);
            float4 d3 = __ldcs(W3 + kb);
            float4 e0 = __ldcs(R0 + kb);
            float4 e1 = __ldcs(R1 + kb);
            float4 e2 = __ldcs(R2 + kb);
            float4 e3 = __ldcs(R3 + kb);

            // ---- compute phase ----
            accA[0] += a0.x * xa.x + a0.y * xa.y + a0.z * xa.z + a0.w * xa.w;
            accA[1] += a1.x * xa.x + a1.y * xa.y + a1.z * xa.z + a1.w * xa.w;
            accA[2] += a2.x * xa.x + a2.y * xa.y + a2.z * xa.z + a2.w * xa.w;
            accA[3] += a3.x * xa.x + a3.y * xa.y + a3.z * xa.z + a3.w * xa.w;
            accA[4] += c0.x * ha.x + c0.y * ha.y + c0.z * ha.z + c0.w * ha.w;
            accA[5] += c1.x * ha.x + c1.y * ha.y + c1.z * ha.z + c1.w * ha.w;
            accA[6] += c2.x * ha.x + c2.y * ha.y + c2.z * ha.z + c2.w * ha.w;
            accA[7] += c3.x * ha.x + c3.y * ha.y + c3.z * ha.z + c3.w * ha.w;

            accB[0] += d0.x * xb.x + d0.y * xb.y + d0.z * xb.z + d0.w * xb.w;
            accB[1] += d1.x * xb.x + d1.y * xb.y + d1.z * xb.z + d1.w * xb.w;
            accB[2] += d2.x * xb.x + d2.y * xb.y + d2.z * xb.z + d2.w * xb.w;
            accB[3] += d3.x * xb.x + d3.y * xb.y + d3.z * xb.z + d3.w * xb.w;
            accB[4] += e0.x * hb.x + e0.y * hb.y + e0.z * hb.z + e0.w * hb.w;
            accB[5] += e1.x * hb.x + e1.y * hb.y + e1.z * hb.z + e1.w * hb.w;
            accB[6] += e2.x * hb.x + e2.y * hb.y + e2.z * hb.z + e2.w * hb.w;
            accB[7] += e3.x * hb.x + e3.y * hb.y + e3.z * hb.z + e3.w * hb.w;
        }

        float acc[8];
#pragma unroll
        for (int g = 0; g < 8; ++g) acc[g] = accA[g] + accB[g];

        // folded warp reduction: 9 shuffles for all 8 gates
        warp_reduce8_store(acc, red[warp], lane);
        __syncthreads();

        if (warp == 0) {
            float tot = 0.0f;
            if (lane < 8) {
#pragma unroll
                for (int w = 0; w < NWARP; ++w) tot += red[w][lane];
            }
            float s_wi = __shfl_sync(0xFFFFFFFFu, tot, 0);
            float s_wf = __shfl_sync(0xFFFFFFFFu, tot, 1);
            float s_wo = __shfl_sync(0xFFFFFFFFu, tot, 2);
            float s_wz = __shfl_sync(0xFFFFFFFFu, tot, 3);
            float s_ri = __shfl_sync(0xFFFFFFFFu, tot, 4);
            float s_rf = __shfl_sync(0xFFFFFFFFu, tot, 5);
            float s_ro = __shfl_sync(0xFFFFFFFFu, tot, 6);
            float s_rz = __shfl_sync(0xFFFFFFFFu, tot, 7);

            if (lane == 0) {
                float i_t = s_wi + s_ri + pb_i;
                float f_t = s_wf + s_rf + pb_f;
                float o_t = s_wo + s_ro + pb_o;
                float z_t = s_wz + s_rz + pb_z;

                // stable log_sigmoid(f) = min(f,0) - log(1 + exp(-|f|)); MUFU-fast
                float log_f = fminf(f_t, 0.0f) - __logf(1.0f + __expf(-fabsf(f_t)));
                float m_t = fmaxf(log_f + pmp, i_t);
                float i_p = __expf(i_t - m_t);          // arg <= 0
                float f_p = __expf(log_f + pmp - m_t);  // arg <= 0
                float c_t = f_p * pcp + i_p * fast_tanh(z_t);
                float n_t = f_p * pnp + i_p;
                float sig_o = __fdividef(1.0f, 1.0f + __expf(-o_t));
                float h_t = sig_o * fast_tanh(__fdividef(c_t, n_t));

                out[row]            = h_t;
                out[HDIM + row]     = c_t;
                out[2 * HDIM + row] = n_t;
                out[3 * HDIM + row] = m_t;
            }
        }

        if (rr + 1 < nrows) __syncthreads();   // red[] reuse safety
    }
}

extern "C" void kernel_launch(void* const* d_in, const int* in_sizes, int n_in,
                              void* d_out, int out_size)
{
    const float* x      = (const float*)d_in[0];
    const float* h_prev = (const float*)d_in[1];
    const float* c_prev = (const float*)d_in[2];
    const float* n_prev = (const float*)d_in[3];
    const float* m_prev = (const float*)d_in[4];
    const float* w_i    = (const float*)d_in[5];
    const float* w_f    = (const float*)d_in[6];
    const float* w_o    = (const float*)d_in[7];
    const float* w_z    = (const float*)d_in[8];
    const float* r_i    = (const float*)d_in[9];
    const float* r_f    = (const float*)d_in[10];
    const float* r_o    = (const float*)d_in[11];
    const float* r_z    = (const float*)d_in[12];
    const float* b_i    = (const float*)d_in[13];
    const float* b_f    = (const float*)d_in[14];
    const float* b_o    = (const float*)d_in[15];
    const float* b_z    = (const float*)d_in[16];
    float* out = (float*)d_out;

    slstm_row_kernel<<<GRID, TPB>>>(x, h_prev, c_prev, n_prev, m_prev,
                                    w_i, w_f, w_o, w_z,
                                    r_i, r_f, r_o, r_z,
                                    b_i, b_f, b_o, b_z, out);
}

// round 17
// speedup vs baseline: 1.0119x; 1.0119x over previous
#include <cuda_runtime.h>
#include <math.h>

#define HDIM 4096
#define IDIM 4096
#define TPB  256
#define NWARP (TPB / 32)

// fast tanh via MUFU-based __expf: rel err ~1e-6, saturates correctly at +/-1
__device__ __forceinline__ float fast_tanh(float v) {
    float e = __expf(2.0f * v);          // inf for large v -> result 1
    return 1.0f - __fdividef(2.0f, e + 1.0f);
}

// Folded multi-value warp reduction: 8 gate sums in 9 shuffles.
// On exit, lanes with (lane&3)==0 hold gate g = bit2(lane) | bit3(lane)<<1 | bit4(lane)<<2.
__device__ __forceinline__ void warp_reduce8_store(const float* acc, float* dst, int lane)
{
    const bool lo16 = (lane & 16) == 0;
    float v[4];
#pragma unroll
    for (int g = 0; g < 4; ++g) {
        float keep = lo16 ? acc[g]     : acc[g + 4];
        float send = lo16 ? acc[g + 4] : acc[g];
        v[g] = keep + __shfl_xor_sync(0xFFFFFFFFu, send, 16);
    }
    const bool lo8 = (lane & 8) == 0;
    float u[2];
#pragma unroll
    for (int g = 0; g < 2; ++g) {
        float keep = lo8 ? v[g]     : v[g + 2];
        float send = lo8 ? v[g + 2] : v[g];
        u[g] = keep + __shfl_xor_sync(0xFFFFFFFFu, send, 8);
    }
    const bool lo4 = (lane & 4) == 0;
    float keep = lo4 ? u[0] : u[1];
    float send = lo4 ? u[1] : u[0];
    float w = keep + __shfl_xor_sync(0xFFFFFFFFu, send, 4);
    w += __shfl_xor_sync(0xFFFFFFFFu, w, 2);
    w += __shfl_xor_sync(0xFFFFFFFFu, w, 1);

    const int g = ((lane >> 2) & 1) | (((lane >> 3) & 1) << 1) | (((lane >> 4) & 1) << 2);
    if ((lane & 3) == 0) dst[g] = w;
}

__global__ __launch_bounds__(TPB, 3) void slstm_row_kernel(
    const float* __restrict__ x,
    const float* __restrict__ h_prev,
    const float* __restrict__ c_prev,
    const float* __restrict__ n_prev,
    const float* __restrict__ m_prev,
    const float* __restrict__ w_i,
    const float* __restrict__ w_f,
    const float* __restrict__ w_o,
    const float* __restrict__ w_z,
    const float* __restrict__ r_i,
    const float* __restrict__ r_f,
    const float* __restrict__ r_o,
    const float* __restrict__ r_z,
    const float* __restrict__ b_i,
    const float* __restrict__ b_f,
    const float* __restrict__ b_o,
    const float* __restrict__ b_z,
    float* __restrict__ out)
{
    const int row = blockIdx.x;
    const int tid = threadIdx.x;
    const int lane = tid & 31;
    const int warp = tid >> 5;

    // ---- prefetch gating scalars early (thread 0); latency hides under mainloop ----
    float pb_i = 0.f, pb_f = 0.f, pb_o = 0.f, pb_z = 0.f, pmp = 0.f, pcp = 0.f, pnp = 0.f;
    if (tid == 0) {
        pb_i = __ldg(b_i + row);
        pb_f = __ldg(b_f + row);
        pb_o = __ldg(b_o + row);
        pb_z = __ldg(b_z + row);
        pmp  = __ldg(m_prev + row);
        pcp  = __ldg(c_prev + row);
        pnp  = __ldg(n_prev + row);
    }

    const size_t roff = (size_t)row * IDIM;

    const float4* W0 = (const float4*)(w_i + roff);
    const float4* W1 = (const float4*)(w_f + roff);
    const float4* W2 = (const float4*)(w_o + roff);
    const float4* W3 = (const float4*)(w_z + roff);
    const float4* R0 = (const float4*)(r_i + roff);
    const float4* R1 = (const float4*)(r_f + roff);
    const float4* R2 = (const float4*)(r_o + roff);
    const float4* R3 = (const float4*)(r_z + roff);

    const float4* xv4 = (const float4*)x;
    const float4* hv4 = (const float4*)h_prev;

    // dual accumulator banks to break dependency chains
    float accA[8], accB[8];
#pragma unroll
    for (int g = 0; g < 8; ++g) { accA[g] = 0.0f; accB[g] = 0.0f; }

    // IDIM/4 = 1024 float4 / row; TPB=256 -> 4 k-slices, as 2 blocks of 2
    // slices with 20 loads front-batched per block (proven schedule).
#pragma unroll
    for (int blk = 0; blk < 2; ++blk) {
        const int ka = (2 * blk + 0) * TPB + tid;
        const int kb = (2 * blk + 1) * TPB + tid;

        // ---- front-batched loads (20 x LDG.128) ----
        float4 xa = __ldg(xv4 + ka);
        float4 ha = __ldg(hv4 + ka);
        float4 xb = __ldg(xv4 + kb);
        float4 hb = __ldg(hv4 + kb);

        float4 a0 = __ldcs(W0 + ka);
        float4 a1 = __ldcs(W1 + ka);
        float4 a2 = __ldcs(W2 + ka);
        float4 a3 = __ldcs(W3 + ka);
        float4 c0 = __ldcs(R0 + ka);
        float4 c1 = __ldcs(R1 + ka);
        float4 c2 = __ldcs(R2 + ka);
        float4 c3 = __ldcs(R3 + ka);

        float4 d0 = __ldcs(W0 + kb);
        float4 d1 = __ldcs(W1 + kb);
        float4 d2 = __ldcs(W2 + kb);
        float4 d3 = __ldcs(W3 + kb);
        float4 e0 = __ldcs(R0 + kb);
        float4 e1 = __ldcs(R1 + kb);
        float4 e2 = __ldcs(R2 + kb);
        float4 e3 = __ldcs(R3 + kb);

        // ---- compute phase ----
        accA[0] += a0.x * xa.x + a0.y * xa.y + a0.z * xa.z + a0.w * xa.w;
        accA[1] += a1.x * xa.x + a1.y * xa.y + a1.z * xa.z + a1.w * xa.w;
        accA[2] += a2.x * xa.x + a2.y * xa.y + a2.z * xa.z + a2.w * xa.w;
        accA[3] += a3.x * xa.x + a3.y * xa.y + a3.z * xa.z + a3.w * xa.w;
        accA[4] += c0.x * ha.x + c0.y * ha.y + c0.z * ha.z + c0.w * ha.w;
        accA[5] += c1.x * ha.x + c1.y * ha.y + c1.z * ha.z + c1.w * ha.w;
        accA[6] += c2.x * ha.x + c2.y * ha.y + c2.z * ha.z + c2.w * ha.w;
        accA[7] += c3.x * ha.x + c3.y * ha.y + c3.z * ha.z + c3.w * ha.w;

        accB[0] += d0.x * xb.x + d0.y * xb.y + d0.z * xb.z + d0.w * xb.w;
        accB[1] += d1.x * xb.x + d1.y * xb.y + d1.z * xb.z + d1.w * xb.w;
        accB[2] += d2.x * xb.x + d2.y * xb.y + d2.z * xb.z + d2.w * xb.w;
        accB[3] += d3.x * xb.x + d3.y * xb.y + d3.z * xb.z + d3.w * xb.w;
        accB[4] += e0.x * hb.x + e0.y * hb.y + e0.z * hb.z + e0.w * hb.w;
        accB[5] += e1.x * hb.x + e1.y * hb.y + e1.z * hb.z + e1.w * hb.w;
        accB[6] += e2.x * hb.x + e2.y * hb.y + e2.z * hb.z + e2.w * hb.w;
        accB[7] += e3.x * hb.x + e3.y * hb.y + e3.z * hb.z + e3.w * hb.w;
    }

    float acc[8];
#pragma unroll
    for (int g = 0; g < 8; ++g) acc[g] = accA[g] + accB[g];

    // folded warp reduction: 9 shuffles for all 8 gates
    __shared__ float red[NWARP][8];
    warp_reduce8_store(acc, red[warp], lane);
    __syncthreads();

    if (warp == 0) {
        float tot = 0.0f;
        if (lane < 8) {
#pragma unroll
            for (int w = 0; w < NWARP; ++w) tot += red[w][lane];
        }
        float s_wi = __shfl_sync(0xFFFFFFFFu, tot, 0);
        float s_wf = __shfl_sync(0xFFFFFFFFu, tot, 1);
        float s_wo = __shfl_sync(0xFFFFFFFFu, tot, 2);
        float s_wz = __shfl_sync(0xFFFFFFFFu, tot, 3);
        float s_ri = __shfl_sync(0xFFFFFFFFu, tot, 4);
        float s_rf = __shfl_sync(0xFFFFFFFFu, tot, 5);
        float s_ro = __shfl_sync(0xFFFFFFFFu, tot, 6);
        float s_rz = __shfl_sync(0xFFFFFFFFu, tot, 7);

        if (lane == 0) {
            float i_t = s_wi + s_ri + pb_i;
            float f_t = s_wf + s_rf + pb_f;
            float o_t = s_wo + s_ro + pb_o;
            float z_t = s_wz + s_rz + pb_z;

            // stable log_sigmoid(f) = min(f,0) - log(1 + exp(-|f|)); MUFU-fast
            float log_f = fminf(f_t, 0.0f) - __logf(1.0f + __expf(-fabsf(f_t)));
            float m_t = fmaxf(log_f + pmp, i_t);
            float i_p = __expf(i_t - m_t);          // arg <= 0
            float f_p = __expf(log_f + pmp - m_t);  // arg <= 0
            float c_t = f_p * pcp + i_p * fast_tanh(z_t);
            float n_t = f_p * pnp + i_p;
            float sig_o = __fdividef(1.0f, 1.0f + __expf(-o_t));
            float h_t = sig_o * fast_tanh(__fdividef(c_t, n_t));

            out[row]            = h_t;
            out[HDIM + row]     = c_t;
            out[2 * HDIM + row] = n_t;
            out[3 * HDIM + row] = m_t;
        }
    }
}

extern "C" void kernel_launch(void* const* d_in, const int* in_sizes, int n_in,
                              void* d_out, int out_size)
{
    const float* x      = (const float*)d_in[0];
    const float* h_prev = (const float*)d_in[1];
    const float* c_prev = (const float*)d_in[2];
    const float* n_prev = (const float*)d_in[3];
    const float* m_prev = (const float*)d_in[4];
    const float* w_i    = (const float*)d_in[5];
    const float* w_f    = (const float*)d_in[6];
    const float* w_o    = (const float*)d_in[7];
    const float* w_z    = (const float*)d_in[8];
    const float* r_i    = (const float*)d_in[9];
    const float* r_f    = (const float*)d_in[10];
    const float* r_o    = (const float*)d_in[11];
    const float* r_z    = (const float*)d_in[12];
    const float* b_i    = (const float*)d_in[13];
    const float* b_f    = (const float*)d_in[14];
    const float* b_o    = (const float*)d_in[15];
    const float* b_z    = (const float*)d_in[16];
    float* out = (float*)d_out;

    slstm_row_kernel<<<HDIM, TPB>>>(x, h_prev, c_prev, n_prev, m_prev,
                                    w_i, w_f, w_o, w_z,
                                    r_i, r_f, r_o, r_z,
                                    b_i, b_f, b_o, b_z, out);
}